// round 13
// baseline (speedup 1.0000x reference)
#include <cuda_runtime.h>
#include <math.h>

namespace {

constexpr int V  = 3;
constexpr int C  = 32;
constexpr int CD = 8;
constexpr int D  = 32;
constexpr int H  = 128;
constexpr int W  = 160;
constexpr int HW = H * W;
constexpr int KD = 8;            // depths per thread (one quarter of D)
constexpr int NC = C + CD;       // 40 channels (even -> clean pair loop)
constexpr float LAMB = 1.5f;
constexpr float EPSW = 1e-4f;    // wy snap threshold (fp32 noise ~1e-5)

typedef unsigned long long ull;
__device__ __forceinline__ ull pk2(float lo, float hi) {
    ull r; asm("mov.b64 %0,{%1,%2};" : "=l"(r) : "f"(lo), "f"(hi)); return r;
}
__device__ __forceinline__ void upk2(ull v, float& lo, float& hi) {
    asm("mov.b64 {%0,%1},%2;" : "=f"(lo), "=f"(hi) : "l"(v));
}
__device__ __forceinline__ ull fma2_(ull a, ull b, ull c) {
    ull d; asm("fma.rn.f32x2 %0,%1,%2,%3;" : "=l"(d) : "l"(a), "l"(b), "l"(c)); return d;
}
__device__ __forceinline__ ull mul2_(ull a, ull b) {
    ull d; asm("mul.rn.f32x2 %0,%1,%2;" : "=l"(d) : "l"(a), "l"(b)); return d;
}
__device__ __forceinline__ ull add2_(ull a, ull b) {
    ull d; asm("add.rn.f32x2 %0,%1,%2;" : "=l"(d) : "l"(a), "l"(b)); return d;
}

__device__ __forceinline__ void inv4x4(const float* m, float* inv) {
    inv[0]  =  m[5]*m[10]*m[15] - m[5]*m[11]*m[14] - m[9]*m[6]*m[15]
             + m[9]*m[7]*m[14] + m[13]*m[6]*m[11] - m[13]*m[7]*m[10];
    inv[4]  = -m[4]*m[10]*m[15] + m[4]*m[11]*m[14] + m[8]*m[6]*m[15]
             - m[8]*m[7]*m[14] - m[12]*m[6]*m[11] + m[12]*m[7]*m[10];
    inv[8]  =  m[4]*m[9]*m[15] - m[4]*m[11]*m[13] - m[8]*m[5]*m[15]
             + m[8]*m[7]*m[13] + m[12]*m[5]*m[11] - m[12]*m[7]*m[9];
    inv[12] = -m[4]*m[9]*m[14] + m[4]*m[10]*m[13] + m[8]*m[5]*m[14]
             - m[8]*m[6]*m[13] - m[12]*m[5]*m[10] + m[12]*m[6]*m[9];
    inv[1]  = -m[1]*m[10]*m[15] + m[1]*m[11]*m[14] + m[9]*m[2]*m[15]
             - m[9]*m[3]*m[14] - m[13]*m[2]*m[11] + m[13]*m[3]*m[10];
    inv[5]  =  m[0]*m[10]*m[15] - m[0]*m[11]*m[14] - m[8]*m[2]*m[15]
             + m[8]*m[3]*m[14] + m[12]*m[2]*m[11] - m[12]*m[3]*m[10];
    inv[9]  = -m[0]*m[9]*m[15] + m[0]*m[11]*m[13] + m[8]*m[1]*m[15]
             - m[8]*m[3]*m[13] - m[12]*m[1]*m[11] + m[12]*m[3]*m[9];
    inv[13] =  m[0]*m[9]*m[14] - m[0]*m[10]*m[13] - m[8]*m[1]*m[14]
             + m[8]*m[2]*m[13] + m[12]*m[1]*m[10] - m[12]*m[2]*m[9];
    inv[2]  =  m[1]*m[6]*m[15] - m[1]*m[7]*m[14] - m[5]*m[2]*m[15]
             + m[5]*m[3]*m[14] + m[13]*m[2]*m[7] - m[13]*m[3]*m[6];
    inv[6]  = -m[0]*m[6]*m[15] + m[0]*m[7]*m[14] + m[4]*m[2]*m[15]
             - m[4]*m[3]*m[14] - m[12]*m[2]*m[7] + m[12]*m[3]*m[6];
    inv[10] =  m[0]*m[5]*m[15] - m[0]*m[7]*m[13] - m[4]*m[1]*m[15]
             + m[4]*m[3]*m[13] + m[12]*m[1]*m[7] - m[12]*m[3]*m[5];
    inv[14] = -m[0]*m[5]*m[14] + m[0]*m[6]*m[13] + m[4]*m[1]*m[14]
             - m[4]*m[2]*m[13] - m[12]*m[1]*m[6] + m[12]*m[2]*m[5];
    inv[3]  = -m[1]*m[6]*m[11] + m[1]*m[7]*m[10] + m[5]*m[2]*m[11]
             - m[5]*m[3]*m[10] - m[9]*m[2]*m[7] + m[9]*m[3]*m[6];
    inv[7]  =  m[0]*m[6]*m[11] - m[0]*m[7]*m[10] - m[4]*m[2]*m[11]
             + m[4]*m[3]*m[10] + m[8]*m[2]*m[7] - m[8]*m[3]*m[6];
    inv[11] = -m[0]*m[5]*m[11] + m[0]*m[7]*m[9] + m[4]*m[1]*m[11]
             - m[4]*m[3]*m[9] - m[8]*m[1]*m[7] + m[8]*m[3]*m[5];
    inv[15] =  m[0]*m[5]*m[10] - m[0]*m[6]*m[9] - m[4]*m[1]*m[10]
             + m[4]*m[2]*m[9] + m[8]*m[1]*m[6] - m[8]*m[2]*m[5];
    float det = m[0]*inv[0] + m[1]*inv[4] + m[2]*inv[8] + m[3]*inv[12];
    float id = 1.0f / det;
    for (int i = 0; i < 16; i++) inv[i] *= id;
}

// Channel c -> (ref, src1, src2) plane base pointers.
__device__ __forceinline__ void chan_ptrs(
    int c, const float* feat, const float* deps,
    const float*& r, const float*& q1, const float*& q2)
{
    if (c < C) {
        r  = feat + c * HW;
        q1 = feat + (C + c) * HW;
        q2 = feat + (2 * C + c) * HW;
    } else {
        int cc = c - C;
        r  = deps + cc * HW;
        q1 = deps + (CD + cc) * HW;
        q2 = deps + (2 * CD + cc) * HW;
    }
}

// ---------------------------------------------------------------------------
// Fully fused kernel. Block = 128 threads = 32 pixels x 4 depth-quarters.
// Fast path: BLOCK-level cooperative staging of (tap, tap+1) pair tables +
// ref-pixel row, 4-deep ring, channels processed in PAIRS with ONE
// __syncthreads per pair (20 barriers instead of 40, 2 channels of ILP
// between syncs). Taps = 1 LDS.64 each; variance math in f32x2. Exact
// register-lean 4-corner fallback. Softmax + moments fused via SMEM.
// ---------------------------------------------------------------------------
__global__ void __launch_bounds__(128, 5) depthnet_kernel(
    const float* __restrict__ feat,    // (V, C, H, W)
    const float* __restrict__ deps,    // (V, CD, H, W)
    const float* __restrict__ dvals,   // (D, H, W)
    const float* __restrict__ regw,    // (40)
    const float* __restrict__ proj,    // (V, 4, 4)
    float* __restrict__ out)           // [depth HW | exp_var HW | prob D*HW]
{
    __shared__ float  sM[2][12];
    __shared__ float  sRW[NC];             // original weights (fallback)
    __shared__ float  sRW2[NC];            // * 2/9 (fast path)
    __shared__ float2 sPairB[4][2][64];    // [buf][view][pair] block-shared
    __shared__ float  sRv[4][32];          // [buf][pixel] ref values
    __shared__ int    sMn[4][2];
    __shared__ int    sOk[4];
    __shared__ int    sOk2[4];
    __shared__ float  sMx[4][32];
    __shared__ float2 sSP[4][32];
    __shared__ float  sVr[4][32];

    if (threadIdx.x == 0) {
        float inv[16];
        inv4x4(proj, inv);
        for (int v = 1; v < V; v++) {
            const float* P = proj + v * 16;
            for (int r = 0; r < 3; r++)
                for (int c2 = 0; c2 < 4; c2++) {
                    float s = P[r*4+0]*inv[0*4+c2] + P[r*4+1]*inv[1*4+c2]
                            + P[r*4+2]*inv[2*4+c2] + P[r*4+3]*inv[3*4+c2];
                    if (c2 < 3) sM[v-1][r*3 + c2] = s;
                    else        sM[v-1][9 + r]    = s;
                }
        }
    }
    if (threadIdx.x < NC) {
        float wv = regw[threadIdx.x];
        sRW[threadIdx.x]  = wv;
        sRW2[threadIdx.x] = wv * (2.0f / 9.0f);
    }
    __syncthreads();

    const unsigned FULL = 0xFFFFFFFFu;
    const int tid  = threadIdx.x;
    const int lane = tid & 31;
    const int wrp  = tid >> 5;             // depth quarter 0..3
    const int pixB = blockIdx.x * 32;
    const int pix  = pixB + lane;
    const int d0   = wrp * KD;
    const int y    = pix / W;
    const int x    = pix - y * W;
    const int yW   = y * W;
    const float xf = (float)x, yf = (float)y;

    float wA[2][KD], wB[2][KD];
    int   u0[2][KD];
    bool  ok = true;

#pragma unroll
    for (int kd = 0; kd < KD; kd++) {
        const float dvk = dvals[(d0 + kd) * HW + pix];
#pragma unroll
        for (int v = 0; v < 2; v++) {
            const float* M = sM[v];
            float r0 = M[0] * xf + M[1] * yf + M[2];
            float r1 = M[3] * xf + M[4] * yf + M[5];
            float r2 = M[6] * xf + M[7] * yf + M[8];
            float zx = r0 * dvk + M[9];
            float zy = r1 * dvk + M[10];
            float zz = r2 * dvk + M[11];
            float iz = 1.0f / zz;
            float px = zx * iz;
            float py = zy * iz;

            float x0f = floorf(px), y0f = floorf(py);
            int   x0  = (int)x0f;
            int   y0  = (int)y0f;
            float wx = px - x0f, wy = py - y0f;
            bool  low = (wy <= EPSW);
            int   yr  = low ? y0 : (y0 + 1);
            float rowW = low ? (1.0f - wy) : wy;
            ok = ok && ((wy <= EPSW) || (wy >= 1.0f - EPSW)) && (yr == y);
            float vx0 = (x0 >= 0 && x0 < W) ? 1.0f : 0.0f;
            float vx1 = (x0 + 1 >= 0 && x0 + 1 < W) ? 1.0f : 0.0f;
            wA[v][kd] = (1.0f - wx) * rowW * vx0;
            wB[v][kd] = wx * rowW * vx1;

            int ul = x0 - x;                     // must be warp-uniform
            int ub = __shfl_sync(FULL, ul, 0);
            ok = ok && (ul == ub);
            u0[v][kd] = ub;
        }
    }
    const bool okw = __all_sync(FULL, ok);

    // per-warp min shift per view
    int mnw[2];
#pragma unroll
    for (int v = 0; v < 2; v++) {
        int mn = u0[v][0];
#pragma unroll
        for (int kd = 1; kd < KD; kd++) mn = min(mn, u0[v][kd]);
        mnw[v] = mn;
    }
    if (lane == 0) {
        sMn[wrp][0] = mnw[0];
        sMn[wrp][1] = mnw[1];
        sOk[wrp] = okw ? 1 : 0;
    }
    __syncthreads();

    // block-level window base per view + per-depth table indices
    int mnB[2], col0B[2];
    bool ok2 = (sOk[0] & sOk[1] & sOk[2] & sOk[3]) != 0;
#pragma unroll
    for (int v = 0; v < 2; v++) {
        mnB[v] = min(min(sMn[0][v], sMn[1][v]), min(sMn[2][v], sMn[3][v]));
        col0B[v] = (x - lane) + mnB[v] - 1;    // block-uniform value
    }
    int ls[2][KD];
#pragma unroll
    for (int v = 0; v < 2; v++)
#pragma unroll
        for (int kd = 0; kd < KD; kd++) {
            int dl = u0[v][kd] - mnB[v] + 1;   // >= 1
            ls[v][kd] = lane + dl;
            ok2 = ok2 && (dl <= 32);           // lane+dl <= 63
        }
    if (lane == 0) sOk2[wrp] = ok2 ? 1 : 0;
    __syncthreads();
    const bool fast = (sOk2[0] & sOk2[1] & sOk2[2] & sOk2[3]) != 0;

    float costv[KD];

    if (fast) {
        // cooperative staging: thread t -> view (t>>6), pair (t&63);
        // threads 0-31 additionally stage the ref-pixel row.
        const int sv = tid >> 6;
        const int si = tid & 63;
        const int g0 = yW + min(max(col0B[sv] + si,     0), W - 1);
        const int g1 = yW + min(max(col0B[sv] + si + 1, 0), W - 1);

        auto stage = [&](int c, int buf) {
            const float *r_, *q1_, *q2_;
            chan_ptrs(c, feat, deps, r_, q1_, q2_);
            const float* p = sv ? q2_ : q1_;
            sPairB[buf][sv][si] = make_float2(__ldg(p + g0), __ldg(p + g1));
            if (tid < 32) sRv[buf][tid] = __ldg(r_ + pixB + tid);
        };

        ull COST[KD/2] = {0ull, 0ull, 0ull, 0ull};

        auto compute = [&](int c, int buf) {
            const float rv = sRv[buf][lane];
            const float2* sp0 = sPairB[buf][0];
            const float2* sp1 = sPairB[buf][1];
            float s1[KD], s2[KD];
#pragma unroll
            for (int kd = 0; kd < KD; kd++) {
                float2 t0 = sp0[ls[0][kd]];
                float2 t1 = sp1[ls[1][kd]];
                s1[kd] = wA[0][kd] * t0.x + wB[0][kd] * t0.y;
                s2[kd] = wA[1][kd] * t1.x + wB[1][kd] * t1.y;
            }
            const float w2 = sRW2[c];
            ull RV  = pk2(rv, rv);
            ull RV2 = mul2_(RV, RV);
            ull WC  = pk2(w2, w2);
            ull WCn = pk2(-w2, -w2);
#pragma unroll
            for (int g = 0; g < KD/2; g++) {
                ull S1 = pk2(s1[2*g], s1[2*g+1]);
                ull S2 = pk2(s2[2*g], s2[2*g+1]);
                ull CR = fma2_(RV, add2_(S1, S2), mul2_(S1, S2));
                ull SF = fma2_(S2, S2, fma2_(S1, S1, RV2));
                COST[g] = fma2_(SF, WC,  COST[g]);
                COST[g] = fma2_(CR, WCn, COST[g]);
            }
        };

        stage(0, 0);
        stage(1, 1);
        __syncthreads();

        // Pair loop: stage (c+2, c+3) into bufs (c+2)&3, (c+3)&3 while
        // computing c, c+1 from bufs c&3, (c+1)&3 (disjoint); one barrier
        // per pair covers both staged-visible and buffer-free hazards.
        for (int c = 0; c < NC; c += 2) {
            if (c + 2 < NC) {
                stage(c + 2, (c + 2) & 3);
                stage(c + 3, (c + 3) & 3);
            }
            compute(c,     c & 3);
            compute(c + 1, (c + 1) & 3);
            __syncthreads();
        }

#pragma unroll
        for (int g = 0; g < KD/2; g++)
            upk2(COST[g], costv[2*g], costv[2*g+1]);
    } else {
        // Exact 4-corner bilinear fallback (reference math). Register-lean.
        constexpr float inv3 = 1.0f / 3.0f;
#pragma unroll 1
        for (int kd = 0; kd < KD; kd++) {
            const float dvk = dvals[(d0 + kd) * HW + pix];
            int   lin[2][4];
            float wt[2][4];
#pragma unroll
            for (int v = 0; v < 2; v++) {
                const float* M = sM[v];
                float r0 = M[0] * xf + M[1] * yf + M[2];
                float r1 = M[3] * xf + M[4] * yf + M[5];
                float r2 = M[6] * xf + M[7] * yf + M[8];
                float zx = r0 * dvk + M[9];
                float zy = r1 * dvk + M[10];
                float zz = r2 * dvk + M[11];
                float iz = 1.0f / zz;
                float px = zx * iz;
                float py = zy * iz;
                float x0f = floorf(px), y0f = floorf(py);
                int   x0  = (int)x0f,   y0  = (int)y0f;
                float wx = px - x0f, wy = py - y0f;
                float vx0 = (x0 >= 0  && x0 < W)        ? 1.0f : 0.0f;
                float vx1 = (x0 + 1 >= 0 && x0 + 1 < W) ? 1.0f : 0.0f;
                float vy0 = (y0 >= 0  && y0 < H)        ? 1.0f : 0.0f;
                float vy1 = (y0 + 1 >= 0 && y0 + 1 < H) ? 1.0f : 0.0f;
                wt[v][0] = (1.0f - wx) * (1.0f - wy) * vx0 * vy0;
                wt[v][1] = wx * (1.0f - wy) * vx1 * vy0;
                wt[v][2] = (1.0f - wx) * wy * vx0 * vy1;
                wt[v][3] = wx * wy * vx1 * vy1;
                int cx0 = min(max(x0, 0), W - 1);
                int cx1 = min(max(x0 + 1, 0), W - 1);
                int cy0 = min(max(y0, 0), H - 1);
                int cy1 = min(max(y0 + 1, 0), H - 1);
                lin[v][0] = cy0 * W + cx0;
                lin[v][1] = cy0 * W + cx1;
                lin[v][2] = cy1 * W + cx0;
                lin[v][3] = cy1 * W + cx1;
            }
            float cost = 0.0f;
#pragma unroll 1
            for (int c = 0; c < NC; c++) {
                const float* base;
                const float* p1;
                const float* p2;
                chan_ptrs(c, feat, deps, base, p1, p2);
                const float rv = base[pix];
                float s1 = p1[lin[0][0]] * wt[0][0] + p1[lin[0][1]] * wt[0][1]
                         + p1[lin[0][2]] * wt[0][2] + p1[lin[0][3]] * wt[0][3];
                float s2 = p2[lin[1][0]] * wt[1][0] + p2[lin[1][1]] * wt[1][1]
                         + p2[lin[1][2]] * wt[1][2] + p2[lin[1][3]] * wt[1][3];
                float s  = rv + s1 + s2;
                float sq = rv * rv + s1 * s1 + s2 * s2;
                float sm = s * inv3;
                cost += sRW[c] * (sq * inv3 - sm * sm);
            }
            costv[kd] = cost;
        }
    }

    // ---------------- fused softmax + moments across the 4 quarters --------
    float m8 = costv[0];
#pragma unroll
    for (int j = 1; j < KD; j++) m8 = fmaxf(m8, costv[j]);
    sMx[wrp][lane] = m8;
    __syncthreads();
    float m = fmaxf(fmaxf(sMx[0][lane], sMx[1][lane]),
                    fmaxf(sMx[2][lane], sMx[3][lane]));

    float dvr[KD];
#pragma unroll
    for (int j = 0; j < KD; j++) dvr[j] = dvals[(d0 + j) * HW + pix];

    float S = 0.0f, P = 0.0f;
#pragma unroll
    for (int j = 0; j < KD; j++) {
        float e = __expf(costv[j] - m);
        costv[j] = e;
        S += e;
        P += e * dvr[j];
    }
    sSP[wrp][lane] = make_float2(S, P);
    __syncthreads();
    float St = 0.0f, Pt = 0.0f;
#pragma unroll
    for (int q = 0; q < 4; q++) {
        float2 sp = sSP[q][lane];
        St += sp.x;
        Pt += sp.y;
    }
    const float isum  = 1.0f / St;
    const float depthv = Pt * isum;

    float v8 = 0.0f;
#pragma unroll
    for (int j = 0; j < KD; j++) {
        float p = costv[j] * isum;
        out[2 * HW + (d0 + j) * HW + pix] = p;
        float t = dvr[j] - depthv;
        v8 += p * t * t;
    }
    sVr[wrp][lane] = v8;
    __syncthreads();
    if (wrp == 0) {
        float var = sVr[0][lane] + sVr[1][lane] + sVr[2][lane] + sVr[3][lane];
        out[pix]      = depthv;
        out[HW + pix] = LAMB * sqrtf(var);
    }
}

} // namespace

extern "C" void kernel_launch(void* const* d_in, const int* in_sizes, int n_in,
                              void* d_out, int out_size) {
    const float* feat  = nullptr;
    const float* deps  = nullptr;
    const float* proj  = nullptr;
    const float* dvals = nullptr;
    const float* regw  = nullptr;
    for (int i = 0; i < n_in; i++) {
        switch (in_sizes[i]) {
            case V * C * HW:  feat  = (const float*)d_in[i]; break;
            case V * CD * HW: deps  = (const float*)d_in[i]; break;
            case V * 16:      proj  = (const float*)d_in[i]; break;
            case D * HW:      dvals = (const float*)d_in[i]; break;
            case C + CD:      regw  = (const float*)d_in[i]; break;
            default: break;
        }
    }
    float* out = (float*)d_out;

    depthnet_kernel<<<HW / 32, 128>>>(feat, deps, dvals, regw, proj, out);
}

// round 14
// speedup vs baseline: 1.1570x; 1.1570x over previous
#include <cuda_runtime.h>
#include <math.h>

namespace {

constexpr int V  = 3;
constexpr int C  = 32;
constexpr int CD = 8;
constexpr int D  = 32;
constexpr int H  = 128;
constexpr int W  = 160;
constexpr int HW = H * W;
constexpr int KD = 8;            // depths per thread (one quarter of D)
constexpr int NC = C + CD;       // 40 channels
constexpr int CG = 8;            // channels per staged group
constexpr int NG = NC / CG;      // 5 groups (0-3 feat, 4 deps)
constexpr float LAMB = 1.5f;
constexpr float EPSW = 1e-4f;    // wy snap threshold (fp32 noise ~1e-5)

typedef unsigned long long ull;
__device__ __forceinline__ ull pk2(float lo, float hi) {
    ull r; asm("mov.b64 %0,{%1,%2};" : "=l"(r) : "f"(lo), "f"(hi)); return r;
}
__device__ __forceinline__ void upk2(ull v, float& lo, float& hi) {
    asm("mov.b64 {%0,%1},%2;" : "=f"(lo), "=f"(hi) : "l"(v));
}
__device__ __forceinline__ ull fma2_(ull a, ull b, ull c) {
    ull d; asm("fma.rn.f32x2 %0,%1,%2,%3;" : "=l"(d) : "l"(a), "l"(b), "l"(c)); return d;
}
__device__ __forceinline__ ull mul2_(ull a, ull b) {
    ull d; asm("mul.rn.f32x2 %0,%1,%2;" : "=l"(d) : "l"(a), "l"(b)); return d;
}
__device__ __forceinline__ ull add2_(ull a, ull b) {
    ull d; asm("add.rn.f32x2 %0,%1,%2;" : "=l"(d) : "l"(a), "l"(b)); return d;
}

__device__ __forceinline__ void inv4x4(const float* m, float* inv) {
    inv[0]  =  m[5]*m[10]*m[15] - m[5]*m[11]*m[14] - m[9]*m[6]*m[15]
             + m[9]*m[7]*m[14] + m[13]*m[6]*m[11] - m[13]*m[7]*m[10];
    inv[4]  = -m[4]*m[10]*m[15] + m[4]*m[11]*m[14] + m[8]*m[6]*m[15]
             - m[8]*m[7]*m[14] - m[12]*m[6]*m[11] + m[12]*m[7]*m[10];
    inv[8]  =  m[4]*m[9]*m[15] - m[4]*m[11]*m[13] - m[8]*m[5]*m[15]
             + m[8]*m[7]*m[13] + m[12]*m[5]*m[11] - m[12]*m[7]*m[9];
    inv[12] = -m[4]*m[9]*m[14] + m[4]*m[10]*m[13] + m[8]*m[5]*m[14]
             - m[8]*m[6]*m[13] - m[12]*m[5]*m[10] + m[12]*m[6]*m[9];
    inv[1]  = -m[1]*m[10]*m[15] + m[1]*m[11]*m[14] + m[9]*m[2]*m[15]
             - m[9]*m[3]*m[14] - m[13]*m[2]*m[11] + m[13]*m[3]*m[10];
    inv[5]  =  m[0]*m[10]*m[15] - m[0]*m[11]*m[14] - m[8]*m[2]*m[15]
             + m[8]*m[3]*m[14] + m[12]*m[2]*m[11] - m[12]*m[3]*m[10];
    inv[9]  = -m[0]*m[9]*m[15] + m[0]*m[11]*m[13] + m[8]*m[1]*m[15]
             - m[8]*m[3]*m[13] - m[12]*m[1]*m[11] + m[12]*m[3]*m[9];
    inv[13] =  m[0]*m[9]*m[14] - m[0]*m[10]*m[13] - m[8]*m[1]*m[14]
             + m[8]*m[2]*m[13] + m[12]*m[1]*m[10] - m[12]*m[2]*m[9];
    inv[2]  =  m[1]*m[6]*m[15] - m[1]*m[7]*m[14] - m[5]*m[2]*m[15]
             + m[5]*m[3]*m[14] + m[13]*m[2]*m[7] - m[13]*m[3]*m[6];
    inv[6]  = -m[0]*m[6]*m[15] + m[0]*m[7]*m[14] + m[4]*m[2]*m[15]
             - m[4]*m[3]*m[14] - m[12]*m[2]*m[7] + m[12]*m[3]*m[6];
    inv[10] =  m[0]*m[5]*m[15] - m[0]*m[7]*m[13] - m[4]*m[1]*m[15]
             + m[4]*m[3]*m[13] + m[12]*m[1]*m[7] - m[12]*m[3]*m[5];
    inv[14] = -m[0]*m[5]*m[14] + m[0]*m[6]*m[13] + m[4]*m[1]*m[14]
             - m[4]*m[2]*m[13] - m[12]*m[1]*m[6] + m[12]*m[2]*m[5];
    inv[3]  = -m[1]*m[6]*m[11] + m[1]*m[7]*m[10] + m[5]*m[2]*m[11]
             - m[5]*m[3]*m[10] - m[9]*m[2]*m[7] + m[9]*m[3]*m[6];
    inv[7]  =  m[0]*m[6]*m[11] - m[0]*m[7]*m[10] - m[4]*m[2]*m[11]
             + m[4]*m[3]*m[10] + m[8]*m[2]*m[7] - m[8]*m[3]*m[6];
    inv[11] = -m[0]*m[5]*m[11] + m[0]*m[7]*m[9] + m[4]*m[1]*m[11]
             - m[4]*m[3]*m[9] - m[8]*m[1]*m[7] + m[8]*m[3]*m[5];
    inv[15] =  m[0]*m[5]*m[10] - m[0]*m[6]*m[9] - m[4]*m[1]*m[10]
             + m[4]*m[2]*m[9] + m[8]*m[1]*m[6] - m[8]*m[2]*m[5];
    float det = m[0]*inv[0] + m[1]*inv[4] + m[2]*inv[8] + m[3]*inv[12];
    float id = 1.0f / det;
    for (int i = 0; i < 16; i++) inv[i] *= id;
}

// Channel c -> (ref, src1, src2) plane base pointers.
__device__ __forceinline__ void chan_ptrs(
    int c, const float* feat, const float* deps,
    const float*& r, const float*& q1, const float*& q2)
{
    if (c < C) {
        r  = feat + c * HW;
        q1 = feat + (C + c) * HW;
        q2 = feat + (2 * C + c) * HW;
    } else {
        int cc = c - C;
        r  = deps + cc * HW;
        q1 = deps + (CD + cc) * HW;
        q2 = deps + (2 * CD + cc) * HW;
    }
}

// ---------------------------------------------------------------------------
// Fully fused kernel. Block = 128 threads = 32 pixels x 4 depth-quarters.
// Fast path: channels processed in GROUPS of 8 with a 2-half staging ring --
// stage the next 8 channels (16 LDGs back-to-back, MLP~16) while computing
// the current 8 from SMEM; ONE __syncthreads per group (6 barriers total).
// Within a group k is compile-time, so all tap LDS use immediate offsets
// (kills the per-channel address ALU). Taps = 1 LDS.64 each; variance math
// in f32x2. Exact register-lean 4-corner fallback. Fused softmax + moments.
// ---------------------------------------------------------------------------
__global__ void __launch_bounds__(128, 5) depthnet_kernel(
    const float* __restrict__ feat,    // (V, C, H, W)
    const float* __restrict__ deps,    // (V, CD, H, W)
    const float* __restrict__ dvals,   // (D, H, W)
    const float* __restrict__ regw,    // (40)
    const float* __restrict__ proj,    // (V, 4, 4)
    float* __restrict__ out)           // [depth HW | exp_var HW | prob D*HW]
{
    __shared__ float  sM[2][12];
    __shared__ float  sRW[NC];             // original weights (fallback)
    __shared__ float  sRW2[NC];            // * 2/9 (fast path)
    __shared__ float2 sPairB[2][CG][2][64];// [half][k][view][pair] (16 KB)
    __shared__ float  sRv[2][CG][32];      // [half][k][pixel] ref values
    __shared__ int    sMn[4][2];
    __shared__ int    sOk[4];
    __shared__ int    sOk2[4];
    __shared__ float  sMx[4][32];
    __shared__ float2 sSP[4][32];
    __shared__ float  sVr[4][32];

    if (threadIdx.x == 0) {
        float inv[16];
        inv4x4(proj, inv);
        for (int v = 1; v < V; v++) {
            const float* P = proj + v * 16;
            for (int r = 0; r < 3; r++)
                for (int c2 = 0; c2 < 4; c2++) {
                    float s = P[r*4+0]*inv[0*4+c2] + P[r*4+1]*inv[1*4+c2]
                            + P[r*4+2]*inv[2*4+c2] + P[r*4+3]*inv[3*4+c2];
                    if (c2 < 3) sM[v-1][r*3 + c2] = s;
                    else        sM[v-1][9 + r]    = s;
                }
        }
    }
    if (threadIdx.x < NC) {
        float wv = regw[threadIdx.x];
        sRW[threadIdx.x]  = wv;
        sRW2[threadIdx.x] = wv * (2.0f / 9.0f);
    }
    __syncthreads();

    const unsigned FULL = 0xFFFFFFFFu;
    const int tid  = threadIdx.x;
    const int lane = tid & 31;
    const int wrp  = tid >> 5;             // depth quarter 0..3
    const int pixB = blockIdx.x * 32;
    const int pix  = pixB + lane;
    const int d0   = wrp * KD;
    const int y    = pix / W;
    const int x    = pix - y * W;
    const int yW   = y * W;
    const float xf = (float)x, yf = (float)y;

    float wA[2][KD], wB[2][KD];
    int   u0[2][KD];
    bool  ok = true;

#pragma unroll
    for (int kd = 0; kd < KD; kd++) {
        const float dvk = dvals[(d0 + kd) * HW + pix];
#pragma unroll
        for (int v = 0; v < 2; v++) {
            const float* M = sM[v];
            float r0 = M[0] * xf + M[1] * yf + M[2];
            float r1 = M[3] * xf + M[4] * yf + M[5];
            float r2 = M[6] * xf + M[7] * yf + M[8];
            float zx = r0 * dvk + M[9];
            float zy = r1 * dvk + M[10];
            float zz = r2 * dvk + M[11];
            float iz = 1.0f / zz;
            float px = zx * iz;
            float py = zy * iz;

            float x0f = floorf(px), y0f = floorf(py);
            int   x0  = (int)x0f;
            int   y0  = (int)y0f;
            float wx = px - x0f, wy = py - y0f;
            bool  low = (wy <= EPSW);
            int   yr  = low ? y0 : (y0 + 1);
            float rowW = low ? (1.0f - wy) : wy;
            ok = ok && ((wy <= EPSW) || (wy >= 1.0f - EPSW)) && (yr == y);
            float vx0 = (x0 >= 0 && x0 < W) ? 1.0f : 0.0f;
            float vx1 = (x0 + 1 >= 0 && x0 + 1 < W) ? 1.0f : 0.0f;
            wA[v][kd] = (1.0f - wx) * rowW * vx0;
            wB[v][kd] = wx * rowW * vx1;

            int ul = x0 - x;                     // must be warp-uniform
            int ub = __shfl_sync(FULL, ul, 0);
            ok = ok && (ul == ub);
            u0[v][kd] = ub;
        }
    }
    const bool okw = __all_sync(FULL, ok);

    // per-warp min shift per view
    int mnw[2];
#pragma unroll
    for (int v = 0; v < 2; v++) {
        int mn = u0[v][0];
#pragma unroll
        for (int kd = 1; kd < KD; kd++) mn = min(mn, u0[v][kd]);
        mnw[v] = mn;
    }
    if (lane == 0) {
        sMn[wrp][0] = mnw[0];
        sMn[wrp][1] = mnw[1];
        sOk[wrp] = okw ? 1 : 0;
    }
    __syncthreads();

    // block-level window base per view + per-depth table indices
    int mnB[2], col0B[2];
    bool ok2 = (sOk[0] & sOk[1] & sOk[2] & sOk[3]) != 0;
#pragma unroll
    for (int v = 0; v < 2; v++) {
        mnB[v] = min(min(sMn[0][v], sMn[1][v]), min(sMn[2][v], sMn[3][v]));
        col0B[v] = (x - lane) + mnB[v] - 1;    // block-uniform value
    }
    int ls[2][KD];
#pragma unroll
    for (int v = 0; v < 2; v++)
#pragma unroll
        for (int kd = 0; kd < KD; kd++) {
            int dl = u0[v][kd] - mnB[v] + 1;   // >= 1
            ls[v][kd] = lane + dl;
            ok2 = ok2 && (dl <= 32);           // lane+dl <= 63
        }
    if (lane == 0) sOk2[wrp] = ok2 ? 1 : 0;
    __syncthreads();
    const bool fast = (sOk2[0] & sOk2[1] & sOk2[2] & sOk2[3]) != 0;

    float costv[KD];

    if (fast) {
        // cooperative staging: thread t -> view (t>>6), pair (t&63);
        // rv staged by all 128 threads (2 of the 8x32 values each).
        const int sv = tid >> 6;
        const int si = tid & 63;
        const int g0 = yW + min(max(col0B[sv] + si,     0), W - 1);
        const int g1 = yW + min(max(col0B[sv] + si + 1, 0), W - 1);

        auto stage_group = [&](int cg, int half) {
#pragma unroll
            for (int k = 0; k < CG; k++) {
                const float *r_, *q1_, *q2_;
                chan_ptrs(cg + k, feat, deps, r_, q1_, q2_);
                const float* p = sv ? q2_ : q1_;
                sPairB[half][k][sv][si] =
                    make_float2(__ldg(p + g0), __ldg(p + g1));
            }
#pragma unroll
            for (int r = 0; r < 2; r++) {
                int idx = tid + r * 128;       // 0..255 = 8 ch x 32 px
                int ch = idx >> 5;
                int px = idx & 31;
                const float *r_, *q1_, *q2_;
                chan_ptrs(cg + ch, feat, deps, r_, q1_, q2_);
                sRv[half][ch][px] = __ldg(r_ + pixB + px);
            }
        };

        ull COST[KD/2] = {0ull, 0ull, 0ull, 0ull};

        auto compute_group = [&](int cg, int half) {
#pragma unroll
            for (int k = 0; k < CG; k++) {     // k compile-time -> imm offsets
                const float rv = sRv[half][k][lane];
                const float2* sp0 = sPairB[half][k][0];
                const float2* sp1 = sPairB[half][k][1];
                float s1[KD], s2[KD];
#pragma unroll
                for (int kd = 0; kd < KD; kd++) {
                    float2 t0 = sp0[ls[0][kd]];
                    float2 t1 = sp1[ls[1][kd]];
                    s1[kd] = wA[0][kd] * t0.x + wB[0][kd] * t0.y;
                    s2[kd] = wA[1][kd] * t1.x + wB[1][kd] * t1.y;
                }
                const float w2 = sRW2[cg + k];
                ull RV  = pk2(rv, rv);
                ull RV2 = mul2_(RV, RV);
                ull WC  = pk2(w2, w2);
                ull WCn = pk2(-w2, -w2);
#pragma unroll
                for (int g = 0; g < KD/2; g++) {
                    ull S1 = pk2(s1[2*g], s1[2*g+1]);
                    ull S2 = pk2(s2[2*g], s2[2*g+1]);
                    ull CR = fma2_(RV, add2_(S1, S2), mul2_(S1, S2));
                    ull SF = fma2_(S2, S2, fma2_(S1, S1, RV2));
                    COST[g] = fma2_(SF, WC,  COST[g]);
                    COST[g] = fma2_(CR, WCn, COST[g]);
                }
            }
        };

        stage_group(0, 0);
        __syncthreads();

        for (int gi = 0; gi < NG; gi++) {
            if (gi + 1 < NG) stage_group((gi + 1) * CG, (gi + 1) & 1);
            compute_group(gi * CG, gi & 1);
            __syncthreads();
        }

#pragma unroll
        for (int g = 0; g < KD/2; g++)
            upk2(COST[g], costv[2*g], costv[2*g+1]);
    } else {
        // Exact 4-corner bilinear fallback (reference math). Register-lean.
        constexpr float inv3 = 1.0f / 3.0f;
#pragma unroll 1
        for (int kd = 0; kd < KD; kd++) {
            const float dvk = dvals[(d0 + kd) * HW + pix];
            int   lin[2][4];
            float wt[2][4];
#pragma unroll
            for (int v = 0; v < 2; v++) {
                const float* M = sM[v];
                float r0 = M[0] * xf + M[1] * yf + M[2];
                float r1 = M[3] * xf + M[4] * yf + M[5];
                float r2 = M[6] * xf + M[7] * yf + M[8];
                float zx = r0 * dvk + M[9];
                float zy = r1 * dvk + M[10];
                float zz = r2 * dvk + M[11];
                float iz = 1.0f / zz;
                float px = zx * iz;
                float py = zy * iz;
                float x0f = floorf(px), y0f = floorf(py);
                int   x0  = (int)x0f,   y0  = (int)y0f;
                float wx = px - x0f, wy = py - y0f;
                float vx0 = (x0 >= 0  && x0 < W)        ? 1.0f : 0.0f;
                float vx1 = (x0 + 1 >= 0 && x0 + 1 < W) ? 1.0f : 0.0f;
                float vy0 = (y0 >= 0  && y0 < H)        ? 1.0f : 0.0f;
                float vy1 = (y0 + 1 >= 0 && y0 + 1 < H) ? 1.0f : 0.0f;
                wt[v][0] = (1.0f - wx) * (1.0f - wy) * vx0 * vy0;
                wt[v][1] = wx * (1.0f - wy) * vx1 * vy0;
                wt[v][2] = (1.0f - wx) * wy * vx0 * vy1;
                wt[v][3] = wx * wy * vx1 * vy1;
                int cx0 = min(max(x0, 0), W - 1);
                int cx1 = min(max(x0 + 1, 0), W - 1);
                int cy0 = min(max(y0, 0), H - 1);
                int cy1 = min(max(y0 + 1, 0), H - 1);
                lin[v][0] = cy0 * W + cx0;
                lin[v][1] = cy0 * W + cx1;
                lin[v][2] = cy1 * W + cx0;
                lin[v][3] = cy1 * W + cx1;
            }
            float cost = 0.0f;
#pragma unroll 1
            for (int c = 0; c < NC; c++) {
                const float* base;
                const float* p1;
                const float* p2;
                chan_ptrs(c, feat, deps, base, p1, p2);
                const float rv = base[pix];
                float s1 = p1[lin[0][0]] * wt[0][0] + p1[lin[0][1]] * wt[0][1]
                         + p1[lin[0][2]] * wt[0][2] + p1[lin[0][3]] * wt[0][3];
                float s2 = p2[lin[1][0]] * wt[1][0] + p2[lin[1][1]] * wt[1][1]
                         + p2[lin[1][2]] * wt[1][2] + p2[lin[1][3]] * wt[1][3];
                float s  = rv + s1 + s2;
                float sq = rv * rv + s1 * s1 + s2 * s2;
                float sm = s * inv3;
                cost += sRW[c] * (sq * inv3 - sm * sm);
            }
            costv[kd] = cost;
        }
    }

    // ---------------- fused softmax + moments across the 4 quarters --------
    float m8 = costv[0];
#pragma unroll
    for (int j = 1; j < KD; j++) m8 = fmaxf(m8, costv[j]);
    sMx[wrp][lane] = m8;
    __syncthreads();
    float m = fmaxf(fmaxf(sMx[0][lane], sMx[1][lane]),
                    fmaxf(sMx[2][lane], sMx[3][lane]));

    float dvr[KD];
#pragma unroll
    for (int j = 0; j < KD; j++) dvr[j] = dvals[(d0 + j) * HW + pix];

    float S = 0.0f, P = 0.0f;
#pragma unroll
    for (int j = 0; j < KD; j++) {
        float e = __expf(costv[j] - m);
        costv[j] = e;
        S += e;
        P += e * dvr[j];
    }
    sSP[wrp][lane] = make_float2(S, P);
    __syncthreads();
    float St = 0.0f, Pt = 0.0f;
#pragma unroll
    for (int q = 0; q < 4; q++) {
        float2 sp = sSP[q][lane];
        St += sp.x;
        Pt += sp.y;
    }
    const float isum  = 1.0f / St;
    const float depthv = Pt * isum;

    float v8 = 0.0f;
#pragma unroll
    for (int j = 0; j < KD; j++) {
        float p = costv[j] * isum;
        out[2 * HW + (d0 + j) * HW + pix] = p;
        float t = dvr[j] - depthv;
        v8 += p * t * t;
    }
    sVr[wrp][lane] = v8;
    __syncthreads();
    if (wrp == 0) {
        float var = sVr[0][lane] + sVr[1][lane] + sVr[2][lane] + sVr[3][lane];
        out[pix]      = depthv;
        out[HW + pix] = LAMB * sqrtf(var);
    }
}

} // namespace

extern "C" void kernel_launch(void* const* d_in, const int* in_sizes, int n_in,
                              void* d_out, int out_size) {
    const float* feat  = nullptr;
    const float* deps  = nullptr;
    const float* proj  = nullptr;
    const float* dvals = nullptr;
    const float* regw  = nullptr;
    for (int i = 0; i < n_in; i++) {
        switch (in_sizes[i]) {
            case V * C * HW:  feat  = (const float*)d_in[i]; break;
            case V * CD * HW: deps  = (const float*)d_in[i]; break;
            case V * 16:      proj  = (const float*)d_in[i]; break;
            case D * HW:      dvals = (const float*)d_in[i]; break;
            case C + CD:      regw  = (const float*)d_in[i]; break;
            default: break;
        }
    }
    float* out = (float*)d_out;

    depthnet_kernel<<<HW / 32, 128>>>(feat, deps, dvals, regw, proj, out);
}

// round 15
// speedup vs baseline: 1.2012x; 1.0382x over previous
#include <cuda_runtime.h>
#include <math.h>

namespace {

constexpr int V  = 3;
constexpr int C  = 32;
constexpr int CD = 8;
constexpr int D  = 32;
constexpr int H  = 128;
constexpr int W  = 160;
constexpr int HW = H * W;
constexpr int KD = 8;            // depths per thread (one quarter of D)
constexpr int NC = C + CD;       // 40 channels
constexpr int CG = 10;           // channels per staged group
constexpr int NG = NC / CG;      // 4 groups
constexpr float LAMB = 1.5f;
constexpr float EPSW = 1e-4f;    // wy snap threshold (fp32 noise ~1e-5)

typedef unsigned long long ull;
__device__ __forceinline__ ull pk2(float lo, float hi) {
    ull r; asm("mov.b64 %0,{%1,%2};" : "=l"(r) : "f"(lo), "f"(hi)); return r;
}
__device__ __forceinline__ void upk2(ull v, float& lo, float& hi) {
    asm("mov.b64 {%0,%1},%2;" : "=f"(lo), "=f"(hi) : "l"(v));
}
__device__ __forceinline__ ull fma2_(ull a, ull b, ull c) {
    ull d; asm("fma.rn.f32x2 %0,%1,%2,%3;" : "=l"(d) : "l"(a), "l"(b), "l"(c)); return d;
}
__device__ __forceinline__ ull mul2_(ull a, ull b) {
    ull d; asm("mul.rn.f32x2 %0,%1,%2;" : "=l"(d) : "l"(a), "l"(b)); return d;
}

__device__ __forceinline__ void inv4x4(const float* m, float* inv) {
    inv[0]  =  m[5]*m[10]*m[15] - m[5]*m[11]*m[14] - m[9]*m[6]*m[15]
             + m[9]*m[7]*m[14] + m[13]*m[6]*m[11] - m[13]*m[7]*m[10];
    inv[4]  = -m[4]*m[10]*m[15] + m[4]*m[11]*m[14] + m[8]*m[6]*m[15]
             - m[8]*m[7]*m[14] - m[12]*m[6]*m[11] + m[12]*m[7]*m[10];
    inv[8]  =  m[4]*m[9]*m[15] - m[4]*m[11]*m[13] - m[8]*m[5]*m[15]
             + m[8]*m[7]*m[13] + m[12]*m[5]*m[11] - m[12]*m[7]*m[9];
    inv[12] = -m[4]*m[9]*m[14] + m[4]*m[10]*m[13] + m[8]*m[5]*m[14]
             - m[8]*m[6]*m[13] - m[12]*m[5]*m[10] + m[12]*m[6]*m[9];
    inv[1]  = -m[1]*m[10]*m[15] + m[1]*m[11]*m[14] + m[9]*m[2]*m[15]
             - m[9]*m[3]*m[14] - m[13]*m[2]*m[11] + m[13]*m[3]*m[10];
    inv[5]  =  m[0]*m[10]*m[15] - m[0]*m[11]*m[14] - m[8]*m[2]*m[15]
             + m[8]*m[3]*m[14] + m[12]*m[2]*m[11] - m[12]*m[3]*m[10];
    inv[9]  = -m[0]*m[9]*m[15] + m[0]*m[11]*m[13] + m[8]*m[1]*m[15]
             - m[8]*m[3]*m[13] - m[12]*m[1]*m[11] + m[12]*m[3]*m[9];
    inv[13] =  m[0]*m[9]*m[14] - m[0]*m[10]*m[13] - m[8]*m[1]*m[14]
             + m[8]*m[2]*m[13] + m[12]*m[1]*m[10] - m[12]*m[2]*m[9];
    inv[2]  =  m[1]*m[6]*m[15] - m[1]*m[7]*m[14] - m[5]*m[2]*m[15]
             + m[5]*m[3]*m[14] + m[13]*m[2]*m[7] - m[13]*m[3]*m[6];
    inv[6]  = -m[0]*m[6]*m[15] + m[0]*m[7]*m[14] + m[4]*m[2]*m[15]
             - m[4]*m[3]*m[14] - m[12]*m[2]*m[7] + m[12]*m[3]*m[6];
    inv[10] =  m[0]*m[5]*m[15] - m[0]*m[7]*m[13] - m[4]*m[1]*m[15]
             + m[4]*m[3]*m[13] + m[12]*m[1]*m[7] - m[12]*m[3]*m[5];
    inv[14] = -m[0]*m[5]*m[14] + m[0]*m[6]*m[13] + m[4]*m[1]*m[14]
             - m[4]*m[2]*m[13] - m[12]*m[1]*m[6] + m[12]*m[2]*m[5];
    inv[3]  = -m[1]*m[6]*m[11] + m[1]*m[7]*m[10] + m[5]*m[2]*m[11]
             - m[5]*m[3]*m[10] - m[9]*m[2]*m[7] + m[9]*m[3]*m[6];
    inv[7]  =  m[0]*m[6]*m[11] - m[0]*m[7]*m[10] - m[4]*m[2]*m[11]
             + m[4]*m[3]*m[10] + m[8]*m[2]*m[7] - m[8]*m[3]*m[6];
    inv[11] = -m[0]*m[5]*m[11] + m[0]*m[7]*m[9] + m[4]*m[1]*m[11]
             - m[4]*m[3]*m[9] - m[8]*m[1]*m[7] + m[8]*m[3]*m[5];
    inv[15] =  m[0]*m[5]*m[10] - m[0]*m[6]*m[9] - m[4]*m[1]*m[10]
             + m[4]*m[2]*m[9] + m[8]*m[1]*m[6] - m[8]*m[2]*m[5];
    float det = m[0]*inv[0] + m[1]*inv[4] + m[2]*inv[8] + m[3]*inv[12];
    float id = 1.0f / det;
    for (int i = 0; i < 16; i++) inv[i] *= id;
}

// Channel c -> (ref, src1, src2) plane base pointers.
__device__ __forceinline__ void chan_ptrs(
    int c, const float* feat, const float* deps,
    const float*& r, const float*& q1, const float*& q2)
{
    if (c < C) {
        r  = feat + c * HW;
        q1 = feat + (C + c) * HW;
        q2 = feat + (2 * C + c) * HW;
    } else {
        int cc = c - C;
        r  = deps + cc * HW;
        q1 = deps + (CD + cc) * HW;
        q2 = deps + (2 * CD + cc) * HW;
    }
}

// ---------------------------------------------------------------------------
// Fully fused kernel. Block = 128 threads = 32 pixels x 4 depth-quarters.
// Fast path: channels in groups of 10 with a 2-half staging ring (stage next
// group's 20 LDGs while computing current group; 4 barriers total). Within a
// group k is compile-time -> immediate-offset tap LDS. Variance uses the
// squared-difference identity 3*sum(f^2) - (sum f)^2 = (rv-s1)^2 + (rv-s2)^2
// + (s1-s2)^2, packed f32x2 over depth pairs. Exact register-lean 4-corner
// fallback. Fused softmax + moments. 5 blocks/SM -> single wave.
// ---------------------------------------------------------------------------
__global__ void __launch_bounds__(128, 5) depthnet_kernel(
    const float* __restrict__ feat,    // (V, C, H, W)
    const float* __restrict__ deps,    // (V, CD, H, W)
    const float* __restrict__ dvals,   // (D, H, W)
    const float* __restrict__ regw,    // (40)
    const float* __restrict__ proj,    // (V, 4, 4)
    float* __restrict__ out)           // [depth HW | exp_var HW | prob D*HW]
{
    __shared__ float  sM[2][12];
    __shared__ float  sRW[NC];             // original weights (fallback)
    __shared__ float  sRW9[NC];            // * 1/9 (fast path)
    __shared__ float2 sPairB[2][CG][2][64];// [half][k][view][pair] (20 KB)
    __shared__ float  sRv[2][CG][32];      // [half][k][pixel] ref values
    __shared__ int    sMn[4][2];
    __shared__ int    sOk[4];
    __shared__ int    sOk2[4];
    __shared__ float  sMx[4][32];
    __shared__ float2 sSP[4][32];
    __shared__ float  sVr[4][32];

    if (threadIdx.x == 0) {
        float inv[16];
        inv4x4(proj, inv);
        for (int v = 1; v < V; v++) {
            const float* P = proj + v * 16;
            for (int r = 0; r < 3; r++)
                for (int c2 = 0; c2 < 4; c2++) {
                    float s = P[r*4+0]*inv[0*4+c2] + P[r*4+1]*inv[1*4+c2]
                            + P[r*4+2]*inv[2*4+c2] + P[r*4+3]*inv[3*4+c2];
                    if (c2 < 3) sM[v-1][r*3 + c2] = s;
                    else        sM[v-1][9 + r]    = s;
                }
        }
    }
    if (threadIdx.x < NC) {
        float wv = regw[threadIdx.x];
        sRW[threadIdx.x]  = wv;
        sRW9[threadIdx.x] = wv * (1.0f / 9.0f);
    }
    __syncthreads();

    const unsigned FULL = 0xFFFFFFFFu;
    const int tid  = threadIdx.x;
    const int lane = tid & 31;
    const int wrp  = tid >> 5;             // depth quarter 0..3
    const int pixB = blockIdx.x * 32;
    const int pix  = pixB + lane;
    const int d0   = wrp * KD;
    const int y    = pix / W;
    const int x    = pix - y * W;
    const int yW   = y * W;
    const float xf = (float)x, yf = (float)y;

    float wA[2][KD], wB[2][KD];
    int   u0[2][KD];
    bool  ok = true;

#pragma unroll
    for (int kd = 0; kd < KD; kd++) {
        const float dvk = dvals[(d0 + kd) * HW + pix];
#pragma unroll
        for (int v = 0; v < 2; v++) {
            const float* M = sM[v];
            float r0 = M[0] * xf + M[1] * yf + M[2];
            float r1 = M[3] * xf + M[4] * yf + M[5];
            float r2 = M[6] * xf + M[7] * yf + M[8];
            float zx = r0 * dvk + M[9];
            float zy = r1 * dvk + M[10];
            float zz = r2 * dvk + M[11];
            float iz = 1.0f / zz;
            float px = zx * iz;
            float py = zy * iz;

            float x0f = floorf(px), y0f = floorf(py);
            int   x0  = (int)x0f;
            int   y0  = (int)y0f;
            float wx = px - x0f, wy = py - y0f;
            bool  low = (wy <= EPSW);
            int   yr  = low ? y0 : (y0 + 1);
            float rowW = low ? (1.0f - wy) : wy;
            ok = ok && ((wy <= EPSW) || (wy >= 1.0f - EPSW)) && (yr == y);
            float vx0 = (x0 >= 0 && x0 < W) ? 1.0f : 0.0f;
            float vx1 = (x0 + 1 >= 0 && x0 + 1 < W) ? 1.0f : 0.0f;
            wA[v][kd] = (1.0f - wx) * rowW * vx0;
            wB[v][kd] = wx * rowW * vx1;

            int ul = x0 - x;                     // must be warp-uniform
            int ub = __shfl_sync(FULL, ul, 0);
            ok = ok && (ul == ub);
            u0[v][kd] = ub;
        }
    }
    const bool okw = __all_sync(FULL, ok);

    // per-warp min shift per view
    int mnw[2];
#pragma unroll
    for (int v = 0; v < 2; v++) {
        int mn = u0[v][0];
#pragma unroll
        for (int kd = 1; kd < KD; kd++) mn = min(mn, u0[v][kd]);
        mnw[v] = mn;
    }
    if (lane == 0) {
        sMn[wrp][0] = mnw[0];
        sMn[wrp][1] = mnw[1];
        sOk[wrp] = okw ? 1 : 0;
    }
    __syncthreads();

    // block-level window base per view + per-depth table indices
    int mnB[2], col0B[2];
    bool ok2 = (sOk[0] & sOk[1] & sOk[2] & sOk[3]) != 0;
#pragma unroll
    for (int v = 0; v < 2; v++) {
        mnB[v] = min(min(sMn[0][v], sMn[1][v]), min(sMn[2][v], sMn[3][v]));
        col0B[v] = (x - lane) + mnB[v] - 1;    // block-uniform value
    }
    int ls[2][KD];
#pragma unroll
    for (int v = 0; v < 2; v++)
#pragma unroll
        for (int kd = 0; kd < KD; kd++) {
            int dl = u0[v][kd] - mnB[v] + 1;   // >= 1
            ls[v][kd] = lane + dl;
            ok2 = ok2 && (dl <= 32);           // lane+dl <= 63
        }
    if (lane == 0) sOk2[wrp] = ok2 ? 1 : 0;
    __syncthreads();
    const bool fast = (sOk2[0] & sOk2[1] & sOk2[2] & sOk2[3]) != 0;

    float costv[KD];

    if (fast) {
        // cooperative staging: thread t -> view (t>>6), pair (t&63);
        // rv staged by all 128 threads (10 ch x 32 px = 320 values).
        const int sv = tid >> 6;
        const int si = tid & 63;
        const int g0 = yW + min(max(col0B[sv] + si,     0), W - 1);
        const int g1 = yW + min(max(col0B[sv] + si + 1, 0), W - 1);

        auto stage_group = [&](int cg, int half) {
#pragma unroll
            for (int k = 0; k < CG; k++) {
                const float *r_, *q1_, *q2_;
                chan_ptrs(cg + k, feat, deps, r_, q1_, q2_);
                const float* p = sv ? q2_ : q1_;
                sPairB[half][k][sv][si] =
                    make_float2(__ldg(p + g0), __ldg(p + g1));
            }
#pragma unroll
            for (int r = 0; r < 3; r++) {
                int idx = tid + r * 128;       // 0..383; need 0..319
                if (idx < CG * 32) {
                    int ch = idx >> 5;
                    int px = idx & 31;
                    const float *r_, *q1_, *q2_;
                    chan_ptrs(cg + ch, feat, deps, r_, q1_, q2_);
                    sRv[half][ch][px] = __ldg(r_ + pixB + px);
                }
            }
        };

        ull COST[KD/2] = {0ull, 0ull, 0ull, 0ull};
        const ull M1 = pk2(-1.0f, -1.0f);

        auto compute_group = [&](int cg, int half) {
#pragma unroll
            for (int k = 0; k < CG; k++) {     // k compile-time -> imm offsets
                const float rv = sRv[half][k][lane];
                const float2* sp0 = sPairB[half][k][0];
                const float2* sp1 = sPairB[half][k][1];
                float s1[KD], s2[KD];
#pragma unroll
                for (int kd = 0; kd < KD; kd++) {
                    float2 t0 = sp0[ls[0][kd]];
                    float2 t1 = sp1[ls[1][kd]];
                    s1[kd] = wA[0][kd] * t0.x + wB[0][kd] * t0.y;
                    s2[kd] = wA[1][kd] * t1.x + wB[1][kd] * t1.y;
                }
                const float w9 = sRW9[cg + k];
                ull RV = pk2(rv, rv);
                ull W9 = pk2(w9, w9);
#pragma unroll
                for (int g = 0; g < KD/2; g++) {
                    ull S1 = pk2(s1[2*g], s1[2*g+1]);
                    ull S2 = pk2(s2[2*g], s2[2*g+1]);
                    // 3*sum(f^2) - (sum f)^2 = d1^2 + d2^2 + d3^2
                    ull D1 = fma2_(S1, M1, RV);      // rv - s1
                    ull D2 = fma2_(S2, M1, RV);      // rv - s2
                    ull D3 = fma2_(S2, M1, S1);      // s1 - s2
                    ull T  = mul2_(D1, D1);
                    T = fma2_(D2, D2, T);
                    T = fma2_(D3, D3, T);
                    COST[g] = fma2_(T, W9, COST[g]);
                }
            }
        };

        stage_group(0, 0);
        __syncthreads();

        for (int gi = 0; gi < NG; gi++) {
            if (gi + 1 < NG) stage_group((gi + 1) * CG, (gi + 1) & 1);
            compute_group(gi * CG, gi & 1);
            __syncthreads();
        }

#pragma unroll
        for (int g = 0; g < KD/2; g++)
            upk2(COST[g], costv[2*g], costv[2*g+1]);
    } else {
        // Exact 4-corner bilinear fallback (reference math). Register-lean.
        constexpr float inv3 = 1.0f / 3.0f;
#pragma unroll 1
        for (int kd = 0; kd < KD; kd++) {
            const float dvk = dvals[(d0 + kd) * HW + pix];
            int   lin[2][4];
            float wt[2][4];
#pragma unroll
            for (int v = 0; v < 2; v++) {
                const float* M = sM[v];
                float r0 = M[0] * xf + M[1] * yf + M[2];
                float r1 = M[3] * xf + M[4] * yf + M[5];
                float r2 = M[6] * xf + M[7] * yf + M[8];
                float zx = r0 * dvk + M[9];
                float zy = r1 * dvk + M[10];
                float zz = r2 * dvk + M[11];
                float iz = 1.0f / zz;
                float px = zx * iz;
                float py = zy * iz;
                float x0f = floorf(px), y0f = floorf(py);
                int   x0  = (int)x0f,   y0  = (int)y0f;
                float wx = px - x0f, wy = py - y0f;
                float vx0 = (x0 >= 0  && x0 < W)        ? 1.0f : 0.0f;
                float vx1 = (x0 + 1 >= 0 && x0 + 1 < W) ? 1.0f : 0.0f;
                float vy0 = (y0 >= 0  && y0 < H)        ? 1.0f : 0.0f;
                float vy1 = (y0 + 1 >= 0 && y0 + 1 < H) ? 1.0f : 0.0f;
                wt[v][0] = (1.0f - wx) * (1.0f - wy) * vx0 * vy0;
                wt[v][1] = wx * (1.0f - wy) * vx1 * vy0;
                wt[v][2] = (1.0f - wx) * wy * vx0 * vy1;
                wt[v][3] = wx * wy * vx1 * vy1;
                int cx0 = min(max(x0, 0), W - 1);
                int cx1 = min(max(x0 + 1, 0), W - 1);
                int cy0 = min(max(y0, 0), H - 1);
                int cy1 = min(max(y0 + 1, 0), H - 1);
                lin[v][0] = cy0 * W + cx0;
                lin[v][1] = cy0 * W + cx1;
                lin[v][2] = cy1 * W + cx0;
                lin[v][3] = cy1 * W + cx1;
            }
            float cost = 0.0f;
#pragma unroll 1
            for (int c = 0; c < NC; c++) {
                const float* base;
                const float* p1;
                const float* p2;
                chan_ptrs(c, feat, deps, base, p1, p2);
                const float rv = base[pix];
                float s1 = p1[lin[0][0]] * wt[0][0] + p1[lin[0][1]] * wt[0][1]
                         + p1[lin[0][2]] * wt[0][2] + p1[lin[0][3]] * wt[0][3];
                float s2 = p2[lin[1][0]] * wt[1][0] + p2[lin[1][1]] * wt[1][1]
                         + p2[lin[1][2]] * wt[1][2] + p2[lin[1][3]] * wt[1][3];
                float s  = rv + s1 + s2;
                float sq = rv * rv + s1 * s1 + s2 * s2;
                float sm = s * inv3;
                cost += sRW[c] * (sq * inv3 - sm * sm);
            }
            costv[kd] = cost;
        }
    }

    // ---------------- fused softmax + moments across the 4 quarters --------
    float m8 = costv[0];
#pragma unroll
    for (int j = 1; j < KD; j++) m8 = fmaxf(m8, costv[j]);
    sMx[wrp][lane] = m8;
    __syncthreads();
    float m = fmaxf(fmaxf(sMx[0][lane], sMx[1][lane]),
                    fmaxf(sMx[2][lane], sMx[3][lane]));

    float dvr[KD];
#pragma unroll
    for (int j = 0; j < KD; j++) dvr[j] = dvals[(d0 + j) * HW + pix];

    float S = 0.0f, P = 0.0f;
#pragma unroll
    for (int j = 0; j < KD; j++) {
        float e = __expf(costv[j] - m);
        costv[j] = e;
        S += e;
        P += e * dvr[j];
    }
    sSP[wrp][lane] = make_float2(S, P);
    __syncthreads();
    float St = 0.0f, Pt = 0.0f;
#pragma unroll
    for (int q = 0; q < 4; q++) {
        float2 sp = sSP[q][lane];
        St += sp.x;
        Pt += sp.y;
    }
    const float isum  = 1.0f / St;
    const float depthv = Pt * isum;

    float v8 = 0.0f;
#pragma unroll
    for (int j = 0; j < KD; j++) {
        float p = costv[j] * isum;
        out[2 * HW + (d0 + j) * HW + pix] = p;
        float t = dvr[j] - depthv;
        v8 += p * t * t;
    }
    sVr[wrp][lane] = v8;
    __syncthreads();
    if (wrp == 0) {
        float var = sVr[0][lane] + sVr[1][lane] + sVr[2][lane] + sVr[3][lane];
        out[pix]      = depthv;
        out[HW + pix] = LAMB * sqrtf(var);
    }
}

} // namespace

extern "C" void kernel_launch(void* const* d_in, const int* in_sizes, int n_in,
                              void* d_out, int out_size) {
    const float* feat  = nullptr;
    const float* deps  = nullptr;
    const float* proj  = nullptr;
    const float* dvals = nullptr;
    const float* regw  = nullptr;
    for (int i = 0; i < n_in; i++) {
        switch (in_sizes[i]) {
            case V * C * HW:  feat  = (const float*)d_in[i]; break;
            case V * CD * HW: deps  = (const float*)d_in[i]; break;
            case V * 16:      proj  = (const float*)d_in[i]; break;
            case D * HW:      dvals = (const float*)d_in[i]; break;
            case C + CD:      regw  = (const float*)d_in[i]; break;
            default: break;
        }
    }
    float* out = (float*)d_out;

    depthnet_kernel<<<HW / 32, 128>>>(feat, deps, dvals, regw, proj, out);
}

// round 16
// speedup vs baseline: 1.2252x; 1.0200x over previous
#include <cuda_runtime.h>
#include <math.h>

namespace {

constexpr int V  = 3;
constexpr int C  = 32;
constexpr int CD = 8;
constexpr int D  = 32;
constexpr int H  = 128;
constexpr int W  = 160;
constexpr int HW = H * W;
constexpr int KD = 8;            // depths per thread (one quarter of D)
constexpr int NC = C + CD;       // 40 channels
constexpr int CG = 10;           // channels per staged group
constexpr int NG = NC / CG;      // 4 groups
constexpr float LAMB = 1.5f;
constexpr float EPSW = 1e-4f;    // wy snap threshold (fp32 noise ~1e-5)

typedef unsigned long long ull;
__device__ __forceinline__ ull pk2(float lo, float hi) {
    ull r; asm("mov.b64 %0,{%1,%2};" : "=l"(r) : "f"(lo), "f"(hi)); return r;
}
__device__ __forceinline__ void upk2(ull v, float& lo, float& hi) {
    asm("mov.b64 {%0,%1},%2;" : "=f"(lo), "=f"(hi) : "l"(v));
}
__device__ __forceinline__ ull fma2_(ull a, ull b, ull c) {
    ull d; asm("fma.rn.f32x2 %0,%1,%2,%3;" : "=l"(d) : "l"(a), "l"(b), "l"(c)); return d;
}
__device__ __forceinline__ ull mul2_(ull a, ull b) {
    ull d; asm("mul.rn.f32x2 %0,%1,%2;" : "=l"(d) : "l"(a), "l"(b)); return d;
}

__device__ __forceinline__ void inv4x4(const float* m, float* inv) {
    inv[0]  =  m[5]*m[10]*m[15] - m[5]*m[11]*m[14] - m[9]*m[6]*m[15]
             + m[9]*m[7]*m[14] + m[13]*m[6]*m[11] - m[13]*m[7]*m[10];
    inv[4]  = -m[4]*m[10]*m[15] + m[4]*m[11]*m[14] + m[8]*m[6]*m[15]
             - m[8]*m[7]*m[14] - m[12]*m[6]*m[11] + m[12]*m[7]*m[10];
    inv[8]  =  m[4]*m[9]*m[15] - m[4]*m[11]*m[13] - m[8]*m[5]*m[15]
             + m[8]*m[7]*m[13] + m[12]*m[5]*m[11] - m[12]*m[7]*m[9];
    inv[12] = -m[4]*m[9]*m[14] + m[4]*m[10]*m[13] + m[8]*m[5]*m[14]
             - m[8]*m[6]*m[13] - m[12]*m[5]*m[10] + m[12]*m[6]*m[9];
    inv[1]  = -m[1]*m[10]*m[15] + m[1]*m[11]*m[14] + m[9]*m[2]*m[15]
             - m[9]*m[3]*m[14] - m[13]*m[2]*m[11] + m[13]*m[3]*m[10];
    inv[5]  =  m[0]*m[10]*m[15] - m[0]*m[11]*m[14] - m[8]*m[2]*m[15]
             + m[8]*m[3]*m[14] + m[12]*m[2]*m[11] - m[12]*m[3]*m[10];
    inv[9]  = -m[0]*m[9]*m[15] + m[0]*m[11]*m[13] + m[8]*m[1]*m[15]
             - m[8]*m[3]*m[13] - m[12]*m[1]*m[11] + m[12]*m[3]*m[9];
    inv[13] =  m[0]*m[9]*m[14] - m[0]*m[10]*m[13] - m[8]*m[1]*m[14]
             + m[8]*m[2]*m[13] + m[12]*m[1]*m[10] - m[12]*m[2]*m[9];
    inv[2]  =  m[1]*m[6]*m[15] - m[1]*m[7]*m[14] - m[5]*m[2]*m[15]
             + m[5]*m[3]*m[14] + m[13]*m[2]*m[7] - m[13]*m[3]*m[6];
    inv[6]  = -m[0]*m[6]*m[15] + m[0]*m[7]*m[14] + m[4]*m[2]*m[15]
             - m[4]*m[3]*m[14] - m[12]*m[2]*m[7] + m[12]*m[3]*m[6];
    inv[10] =  m[0]*m[5]*m[15] - m[0]*m[7]*m[13] - m[4]*m[1]*m[15]
             + m[4]*m[3]*m[13] + m[12]*m[1]*m[7] - m[12]*m[3]*m[5];
    inv[14] = -m[0]*m[5]*m[14] + m[0]*m[6]*m[13] + m[4]*m[1]*m[14]
             - m[4]*m[2]*m[13] - m[12]*m[1]*m[6] + m[12]*m[2]*m[5];
    inv[3]  = -m[1]*m[6]*m[11] + m[1]*m[7]*m[10] + m[5]*m[2]*m[11]
             - m[5]*m[3]*m[10] - m[9]*m[2]*m[7] + m[9]*m[3]*m[6];
    inv[7]  =  m[0]*m[6]*m[11] - m[0]*m[7]*m[10] - m[4]*m[2]*m[11]
             + m[4]*m[3]*m[10] + m[8]*m[2]*m[7] - m[8]*m[3]*m[6];
    inv[11] = -m[0]*m[5]*m[11] + m[0]*m[7]*m[9] + m[4]*m[1]*m[11]
             - m[4]*m[3]*m[9] - m[8]*m[1]*m[7] + m[8]*m[3]*m[5];
    inv[15] =  m[0]*m[5]*m[10] - m[0]*m[6]*m[9] - m[4]*m[1]*m[10]
             + m[4]*m[2]*m[9] + m[8]*m[1]*m[6] - m[8]*m[2]*m[5];
    float det = m[0]*inv[0] + m[1]*inv[4] + m[2]*inv[8] + m[3]*inv[12];
    float id = 1.0f / det;
    for (int i = 0; i < 16; i++) inv[i] *= id;
}

// Channel c -> (ref, src1, src2) plane base pointers.
__device__ __forceinline__ void chan_ptrs(
    int c, const float* feat, const float* deps,
    const float*& r, const float*& q1, const float*& q2)
{
    if (c < C) {
        r  = feat + c * HW;
        q1 = feat + (C + c) * HW;
        q2 = feat + (2 * C + c) * HW;
    } else {
        int cc = c - C;
        r  = deps + cc * HW;
        q1 = deps + (CD + cc) * HW;
        q2 = deps + (2 * CD + cc) * HW;
    }
}

// ---------------------------------------------------------------------------
// Fully fused kernel. Block = 128 threads = 32 pixels x 4 depth-quarters.
// Fast path: channels in groups of 10, 2-half staging ring (stage next group
// while computing current; sync only between groups -> 4 barriers). k is
// compile-time within a group -> immediate-offset tap LDS. Variance via the
// squared-difference identity, packed f32x2. Homography row terms hoisted
// per view; depth values kept in registers through to the softmax tail.
// Exact register-lean 4-corner fallback. Fused softmax + moments.
// ---------------------------------------------------------------------------
__global__ void __launch_bounds__(128, 5) depthnet_kernel(
    const float* __restrict__ feat,    // (V, C, H, W)
    const float* __restrict__ deps,    // (V, CD, H, W)
    const float* __restrict__ dvals,   // (D, H, W)
    const float* __restrict__ regw,    // (40)
    const float* __restrict__ proj,    // (V, 4, 4)
    float* __restrict__ out)           // [depth HW | exp_var HW | prob D*HW]
{
    __shared__ float  sM[2][12];
    __shared__ float  sRW[NC];             // original weights (fallback)
    __shared__ float  sRW9[NC];            // * 1/9 (fast path)
    __shared__ float2 sPairB[2][CG][2][64];// [half][k][view][pair] (20 KB)
    __shared__ float  sRv[2][CG][32];      // [half][k][pixel] ref values
    __shared__ int    sMn[4][2];
    __shared__ int    sOk[4];
    __shared__ int    sOk2[4];
    __shared__ float  sMx[4][32];
    __shared__ float2 sSP[4][32];
    __shared__ float  sVr[4][32];

    if (threadIdx.x == 0) {
        float inv[16];
        inv4x4(proj, inv);
        for (int v = 1; v < V; v++) {
            const float* P = proj + v * 16;
            for (int r = 0; r < 3; r++)
                for (int c2 = 0; c2 < 4; c2++) {
                    float s = P[r*4+0]*inv[0*4+c2] + P[r*4+1]*inv[1*4+c2]
                            + P[r*4+2]*inv[2*4+c2] + P[r*4+3]*inv[3*4+c2];
                    if (c2 < 3) sM[v-1][r*3 + c2] = s;
                    else        sM[v-1][9 + r]    = s;
                }
        }
    }
    if (threadIdx.x < NC) {
        float wv = regw[threadIdx.x];
        sRW[threadIdx.x]  = wv;
        sRW9[threadIdx.x] = wv * (1.0f / 9.0f);
    }
    __syncthreads();

    const unsigned FULL = 0xFFFFFFFFu;
    const int tid  = threadIdx.x;
    const int lane = tid & 31;
    const int wrp  = tid >> 5;             // depth quarter 0..3
    const int pixB = blockIdx.x * 32;
    const int pix  = pixB + lane;
    const int d0   = wrp * KD;
    const int y    = pix / W;
    const int x    = pix - y * W;
    const int yW   = y * W;
    const float xf = (float)x, yf = (float)y;

    // Hoisted per-view homography row terms (depth-invariant).
    float R0[2], R1[2], R2[2], T0[2], T1[2], T2[2];
#pragma unroll
    for (int v = 0; v < 2; v++) {
        const float* M = sM[v];
        R0[v] = M[0] * xf + M[1] * yf + M[2];
        R1[v] = M[3] * xf + M[4] * yf + M[5];
        R2[v] = M[6] * xf + M[7] * yf + M[8];
        T0[v] = M[9]; T1[v] = M[10]; T2[v] = M[11];
    }

    float dv[KD];
    float wA[2][KD], wB[2][KD];
    int   u0[2][KD];
    bool  ok = true;

#pragma unroll
    for (int kd = 0; kd < KD; kd++) {
        dv[kd] = dvals[(d0 + kd) * HW + pix];
#pragma unroll
        for (int v = 0; v < 2; v++) {
            float zx = R0[v] * dv[kd] + T0[v];
            float zy = R1[v] * dv[kd] + T1[v];
            float zz = R2[v] * dv[kd] + T2[v];
            float iz = 1.0f / zz;
            float px = zx * iz;
            float py = zy * iz;

            float x0f = floorf(px), y0f = floorf(py);
            int   x0  = (int)x0f;
            int   y0  = (int)y0f;
            float wx = px - x0f, wy = py - y0f;
            bool  low = (wy <= EPSW);
            int   yr  = low ? y0 : (y0 + 1);
            float rowW = low ? (1.0f - wy) : wy;
            ok = ok && ((wy <= EPSW) || (wy >= 1.0f - EPSW)) && (yr == y);
            float vx0 = (x0 >= 0 && x0 < W) ? 1.0f : 0.0f;
            float vx1 = (x0 + 1 >= 0 && x0 + 1 < W) ? 1.0f : 0.0f;
            wA[v][kd] = (1.0f - wx) * rowW * vx0;
            wB[v][kd] = wx * rowW * vx1;

            int ul = x0 - x;                     // must be warp-uniform
            int ub = __shfl_sync(FULL, ul, 0);
            ok = ok && (ul == ub);
            u0[v][kd] = ub;
        }
    }
    const bool okw = __all_sync(FULL, ok);

    // per-warp min shift per view
    int mnw[2];
#pragma unroll
    for (int v = 0; v < 2; v++) {
        int mn = u0[v][0];
#pragma unroll
        for (int kd = 1; kd < KD; kd++) mn = min(mn, u0[v][kd]);
        mnw[v] = mn;
    }
    if (lane == 0) {
        sMn[wrp][0] = mnw[0];
        sMn[wrp][1] = mnw[1];
        sOk[wrp] = okw ? 1 : 0;
    }
    __syncthreads();

    // block-level window base per view + per-depth table indices
    int mnB[2], col0B[2];
    bool ok2 = (sOk[0] & sOk[1] & sOk[2] & sOk[3]) != 0;
#pragma unroll
    for (int v = 0; v < 2; v++) {
        mnB[v] = min(min(sMn[0][v], sMn[1][v]), min(sMn[2][v], sMn[3][v]));
        col0B[v] = (x - lane) + mnB[v] - 1;    // block-uniform value
    }
    int ls[2][KD];
#pragma unroll
    for (int v = 0; v < 2; v++)
#pragma unroll
        for (int kd = 0; kd < KD; kd++) {
            int dl = u0[v][kd] - mnB[v] + 1;   // >= 1
            ls[v][kd] = lane + dl;
            ok2 = ok2 && (dl <= 32);           // lane+dl <= 63
        }
    if (lane == 0) sOk2[wrp] = ok2 ? 1 : 0;
    __syncthreads();
    const bool fast = (sOk2[0] & sOk2[1] & sOk2[2] & sOk2[3]) != 0;

    float costv[KD];

    if (fast) {
        // cooperative staging: thread t -> view (t>>6), pair (t&63);
        // rv staged by all 128 threads (10 ch x 32 px = 320 values).
        const int sv = tid >> 6;
        const int si = tid & 63;
        const int g0 = yW + min(max(col0B[sv] + si,     0), W - 1);
        const int g1 = yW + min(max(col0B[sv] + si + 1, 0), W - 1);

        auto stage_group = [&](int cg, int half) {
#pragma unroll
            for (int k = 0; k < CG; k++) {
                const float *r_, *q1_, *q2_;
                chan_ptrs(cg + k, feat, deps, r_, q1_, q2_);
                const float* p = sv ? q2_ : q1_;
                sPairB[half][k][sv][si] =
                    make_float2(__ldg(p + g0), __ldg(p + g1));
            }
#pragma unroll
            for (int r = 0; r < 3; r++) {
                int idx = tid + r * 128;       // 0..383; need 0..319
                if (idx < CG * 32) {
                    int ch = idx >> 5;
                    int px = idx & 31;
                    const float *r_, *q1_, *q2_;
                    chan_ptrs(cg + ch, feat, deps, r_, q1_, q2_);
                    sRv[half][ch][px] = __ldg(r_ + pixB + px);
                }
            }
        };

        ull COST[KD/2] = {0ull, 0ull, 0ull, 0ull};
        const ull M1 = pk2(-1.0f, -1.0f);

        auto compute_group = [&](int cg, int half) {
#pragma unroll
            for (int k = 0; k < CG; k++) {     // k compile-time -> imm offsets
                const float rv = sRv[half][k][lane];
                const float2* sp0 = sPairB[half][k][0];
                const float2* sp1 = sPairB[half][k][1];
                float s1[KD], s2[KD];
#pragma unroll
                for (int kd = 0; kd < KD; kd++) {
                    float2 t0 = sp0[ls[0][kd]];
                    float2 t1 = sp1[ls[1][kd]];
                    s1[kd] = wA[0][kd] * t0.x + wB[0][kd] * t0.y;
                    s2[kd] = wA[1][kd] * t1.x + wB[1][kd] * t1.y;
                }
                const float w9 = sRW9[cg + k];
                ull RV = pk2(rv, rv);
                ull W9 = pk2(w9, w9);
#pragma unroll
                for (int g = 0; g < KD/2; g++) {
                    ull S1 = pk2(s1[2*g], s1[2*g+1]);
                    ull S2 = pk2(s2[2*g], s2[2*g+1]);
                    // 3*sum(f^2) - (sum f)^2 = d1^2 + d2^2 + d3^2
                    ull D1 = fma2_(S1, M1, RV);      // rv - s1
                    ull D2 = fma2_(S2, M1, RV);      // rv - s2
                    ull D3 = fma2_(S2, M1, S1);      // s1 - s2
                    ull T  = mul2_(D1, D1);
                    T = fma2_(D2, D2, T);
                    T = fma2_(D3, D3, T);
                    COST[g] = fma2_(T, W9, COST[g]);
                }
            }
        };

        stage_group(0, 0);
        __syncthreads();

        for (int gi = 0; gi < NG; gi++) {
            if (gi + 1 < NG) {
                stage_group((gi + 1) * CG, (gi + 1) & 1);
                compute_group(gi * CG, gi & 1);
                __syncthreads();
            } else {
                compute_group(gi * CG, gi & 1);   // no trailing barrier
            }
        }

#pragma unroll
        for (int g = 0; g < KD/2; g++)
            upk2(COST[g], costv[2*g], costv[2*g+1]);
    } else {
        // Exact 4-corner bilinear fallback (reference math). Register-lean.
        constexpr float inv3 = 1.0f / 3.0f;
#pragma unroll 1
        for (int kd = 0; kd < KD; kd++) {
            const float dvk = dv[kd];
            int   lin[2][4];
            float wt[2][4];
#pragma unroll
            for (int v = 0; v < 2; v++) {
                float zx = R0[v] * dvk + T0[v];
                float zy = R1[v] * dvk + T1[v];
                float zz = R2[v] * dvk + T2[v];
                float iz = 1.0f / zz;
                float px = zx * iz;
                float py = zy * iz;
                float x0f = floorf(px), y0f = floorf(py);
                int   x0  = (int)x0f,   y0  = (int)y0f;
                float wx = px - x0f, wy = py - y0f;
                float vx0 = (x0 >= 0  && x0 < W)        ? 1.0f : 0.0f;
                float vx1 = (x0 + 1 >= 0 && x0 + 1 < W) ? 1.0f : 0.0f;
                float vy0 = (y0 >= 0  && y0 < H)        ? 1.0f : 0.0f;
                float vy1 = (y0 + 1 >= 0 && y0 + 1 < H) ? 1.0f : 0.0f;
                wt[v][0] = (1.0f - wx) * (1.0f - wy) * vx0 * vy0;
                wt[v][1] = wx * (1.0f - wy) * vx1 * vy0;
                wt[v][2] = (1.0f - wx) * wy * vx0 * vy1;
                wt[v][3] = wx * wy * vx1 * vy1;
                int cx0 = min(max(x0, 0), W - 1);
                int cx1 = min(max(x0 + 1, 0), W - 1);
                int cy0 = min(max(y0, 0), H - 1);
                int cy1 = min(max(y0 + 1, 0), H - 1);
                lin[v][0] = cy0 * W + cx0;
                lin[v][1] = cy0 * W + cx1;
                lin[v][2] = cy1 * W + cx0;
                lin[v][3] = cy1 * W + cx1;
            }
            float cost = 0.0f;
#pragma unroll 1
            for (int c = 0; c < NC; c++) {
                const float* base;
                const float* p1;
                const float* p2;
                chan_ptrs(c, feat, deps, base, p1, p2);
                const float rv = base[pix];
                float s1 = p1[lin[0][0]] * wt[0][0] + p1[lin[0][1]] * wt[0][1]
                         + p1[lin[0][2]] * wt[0][2] + p1[lin[0][3]] * wt[0][3];
                float s2 = p2[lin[1][0]] * wt[1][0] + p2[lin[1][1]] * wt[1][1]
                         + p2[lin[1][2]] * wt[1][2] + p2[lin[1][3]] * wt[1][3];
                float s  = rv + s1 + s2;
                float sq = rv * rv + s1 * s1 + s2 * s2;
                float sm = s * inv3;
                cost += sRW[c] * (sq * inv3 - sm * sm);
            }
            costv[kd] = cost;
        }
    }

    // ---------------- fused softmax + moments across the 4 quarters --------
    float m8 = costv[0];
#pragma unroll
    for (int j = 1; j < KD; j++) m8 = fmaxf(m8, costv[j]);
    sMx[wrp][lane] = m8;
    __syncthreads();
    float m = fmaxf(fmaxf(sMx[0][lane], sMx[1][lane]),
                    fmaxf(sMx[2][lane], sMx[3][lane]));

    float S = 0.0f, P = 0.0f;
#pragma unroll
    for (int j = 0; j < KD; j++) {
        float e = __expf(costv[j] - m);
        costv[j] = e;
        S += e;
        P += e * dv[j];
    }
    sSP[wrp][lane] = make_float2(S, P);
    __syncthreads();
    float St = 0.0f, Pt = 0.0f;
#pragma unroll
    for (int q = 0; q < 4; q++) {
        float2 sp = sSP[q][lane];
        St += sp.x;
        Pt += sp.y;
    }
    const float isum  = 1.0f / St;
    const float depthv = Pt * isum;

    float v8 = 0.0f;
#pragma unroll
    for (int j = 0; j < KD; j++) {
        float p = costv[j] * isum;
        out[2 * HW + (d0 + j) * HW + pix] = p;
        float t = dv[j] - depthv;
        v8 += p * t * t;
    }
    sVr[wrp][lane] = v8;
    __syncthreads();
    if (wrp == 0) {
        float var = sVr[0][lane] + sVr[1][lane] + sVr[2][lane] + sVr[3][lane];
        out[pix]      = depthv;
        out[HW + pix] = LAMB * sqrtf(var);
    }
}

} // namespace

extern "C" void kernel_launch(void* const* d_in, const int* in_sizes, int n_in,
                              void* d_out, int out_size) {
    const float* feat  = nullptr;
    const float* deps  = nullptr;
    const float* proj  = nullptr;
    const float* dvals = nullptr;
    const float* regw  = nullptr;
    for (int i = 0; i < n_in; i++) {
        switch (in_sizes[i]) {
            case V * C * HW:  feat  = (const float*)d_in[i]; break;
            case V * CD * HW: deps  = (const float*)d_in[i]; break;
            case V * 16:      proj  = (const float*)d_in[i]; break;
            case D * HW:      dvals = (const float*)d_in[i]; break;
            case C + CD:      regw  = (const float*)d_in[i]; break;
            default: break;
        }
    }
    float* out = (float*)d_out;

    depthnet_kernel<<<HW / 32, 128>>>(feat, deps, dvals, regw, proj, out);
}